// round 5
// baseline (speedup 1.0000x reference)
#include <cuda_runtime.h>

#define NN 50000
#define NE 600000
#define DD 128

// Scratch (device globals — no allocation in kernel_launch).
static __device__ float g_Y[(size_t)NN * 256];    // [N, 256]: cols 0:128 = x@W1a, 128:256 = x@W1b
static __device__ float g_agg[(size_t)NN * DD];   // segment-summed messages

// ---------------- zero agg ----------------
__global__ void zero_agg_kernel() {
    int i = blockIdx.x * blockDim.x + threadIdx.x;
    if (i < NN * DD / 4)
        reinterpret_cast<float4*>(g_agg)[i] = make_float4(0.f, 0.f, 0.f, 0.f);
}

// ---------------- GEMM 1: Y[:, half*128 : half*128+128] = X @ W1[half*128 : half*128+128, :] ----------------
__global__ void __launch_bounds__(256) proj_kernel(const float* __restrict__ X,
                                                   const float* __restrict__ W1) {
    const int half = blockIdx.y;
    const float* B = W1 + half * (128 * 128);
    const int m0 = blockIdx.x * 128;

    __shared__ float As[16][132];   // A tile transposed: As[k][m]
    __shared__ float Bs[16][132];   // B tile: Bs[k][n]

    const int tid  = threadIdx.x;
    const int aRow = tid >> 2;          // 0..63
    const int aCol = (tid & 3) * 4;     // 0,4,8,12
    const int bRow = tid >> 5;          // 0..7
    const int bCol = (tid & 31) * 4;    // 0..124
    const int tr   = (tid >> 4) * 8;    // C-subtile row
    const int tc   = (tid & 15) * 8;    // C-subtile col

    float acc[8][8];
#pragma unroll
    for (int i = 0; i < 8; i++)
#pragma unroll
        for (int j = 0; j < 8; j++) acc[i][j] = 0.f;

    for (int k0 = 0; k0 < 128; k0 += 16) {
#pragma unroll
        for (int p = 0; p < 2; p++) {
            int r  = aRow + p * 64;
            int gr = m0 + r;
            float4 v = make_float4(0.f, 0.f, 0.f, 0.f);
            if (gr < NN)
                v = *reinterpret_cast<const float4*>(X + (size_t)gr * 128 + k0 + aCol);
            As[aCol + 0][r] = v.x;
            As[aCol + 1][r] = v.y;
            As[aCol + 2][r] = v.z;
            As[aCol + 3][r] = v.w;
        }
#pragma unroll
        for (int p = 0; p < 2; p++) {
            int r = bRow + p * 8;
            float4 v = *reinterpret_cast<const float4*>(B + (size_t)(k0 + r) * 128 + bCol);
            *reinterpret_cast<float4*>(&Bs[r][bCol]) = v;
        }
        __syncthreads();
#pragma unroll
        for (int kk = 0; kk < 16; kk++) {
            float a[8], b[8];
            *(float4*)&a[0] = *(const float4*)&As[kk][tr];
            *(float4*)&a[4] = *(const float4*)&As[kk][tr + 4];
            *(float4*)&b[0] = *(const float4*)&Bs[kk][tc];
            *(float4*)&b[4] = *(const float4*)&Bs[kk][tc + 4];
#pragma unroll
            for (int i = 0; i < 8; i++)
#pragma unroll
                for (int j = 0; j < 8; j++)
                    acc[i][j] += a[i] * b[j];
        }
        __syncthreads();
    }

#pragma unroll
    for (int i = 0; i < 8; i++) {
        int gr = m0 + tr + i;
        if (gr < NN) {
            float* out = g_Y + (size_t)gr * 256 + half * 128 + tc;
            *(float4*)(out + 0) = make_float4(acc[i][0], acc[i][1], acc[i][2], acc[i][3]);
            *(float4*)(out + 4) = make_float4(acc[i][4], acc[i][5], acc[i][6], acc[i][7]);
        }
    }
}

// ---------------- Edge pass: agg[dst] += relu(Ya[src] + Yb[dst] + b1) ----------------
__global__ void __launch_bounds__(256) edge_kernel(const int* __restrict__ esrc,
                                                   const int* __restrict__ edst,
                                                   const float* __restrict__ b1) {
    int e = blockIdx.x * 8 + (threadIdx.x >> 5);
    if (e >= NE) return;
    int lane = threadIdx.x & 31;
    int s = __ldg(esrc + e);
    int d = __ldg(edst + e);

    float4 a  = *reinterpret_cast<const float4*>(g_Y + (size_t)s * 256 + lane * 4);
    float4 b  = *reinterpret_cast<const float4*>(g_Y + (size_t)d * 256 + 128 + lane * 4);
    float4 bb = reinterpret_cast<const float4*>(b1)[lane];

    float m0 = fmaxf(a.x + b.x + bb.x, 0.f);
    float m1 = fmaxf(a.y + b.y + bb.y, 0.f);
    float m2 = fmaxf(a.z + b.z + bb.z, 0.f);
    float m3 = fmaxf(a.w + b.w + bb.w, 0.f);

    float* p = g_agg + (size_t)d * DD + lane * 4;
    asm volatile("red.global.add.v4.f32 [%0], {%1, %2, %3, %4};"
                 :: "l"(p), "f"(m0), "f"(m1), "f"(m2), "f"(m3) : "memory");
}

// ---------------- GEMM 2 + epilogue: out = x + relu([x|agg] @ W2 + b2) ----------------
__global__ void __launch_bounds__(256) update_kernel(const float* __restrict__ X,
                                                     const float* __restrict__ W2,
                                                     const float* __restrict__ b2,
                                                     float* __restrict__ out) {
    const int m0 = blockIdx.x * 128;

    __shared__ float As[16][132];
    __shared__ float Bs[16][132];

    const int tid  = threadIdx.x;
    const int aRow = tid >> 2;
    const int aCol = (tid & 3) * 4;
    const int bRow = tid >> 5;
    const int bCol = (tid & 31) * 4;
    const int tr   = (tid >> 4) * 8;
    const int tc   = (tid & 15) * 8;

    float acc[8][8];
#pragma unroll
    for (int i = 0; i < 8; i++)
#pragma unroll
        for (int j = 0; j < 8; j++) acc[i][j] = 0.f;

    for (int k0 = 0; k0 < 256; k0 += 16) {
        const float* Asrc = (k0 < 128) ? X : (const float*)g_agg;
        const int kloc = k0 & 127;
#pragma unroll
        for (int p = 0; p < 2; p++) {
            int r  = aRow + p * 64;
            int gr = m0 + r;
            float4 v = make_float4(0.f, 0.f, 0.f, 0.f);
            if (gr < NN)
                v = *reinterpret_cast<const float4*>(Asrc + (size_t)gr * 128 + kloc + aCol);
            As[aCol + 0][r] = v.x;
            As[aCol + 1][r] = v.y;
            As[aCol + 2][r] = v.z;
            As[aCol + 3][r] = v.w;
        }
#pragma unroll
        for (int p = 0; p < 2; p++) {
            int r = bRow + p * 8;
            float4 v = *reinterpret_cast<const float4*>(W2 + (size_t)(k0 + r) * 128 + bCol);
            *reinterpret_cast<float4*>(&Bs[r][bCol]) = v;
        }
        __syncthreads();
#pragma unroll
        for (int kk = 0; kk < 16; kk++) {
            float a[8], b[8];
            *(float4*)&a[0] = *(const float4*)&As[kk][tr];
            *(float4*)&a[4] = *(const float4*)&As[kk][tr + 4];
            *(float4*)&b[0] = *(const float4*)&Bs[kk][tc];
            *(float4*)&b[4] = *(const float4*)&Bs[kk][tc + 4];
#pragma unroll
            for (int i = 0; i < 8; i++)
#pragma unroll
                for (int j = 0; j < 8; j++)
                    acc[i][j] += a[i] * b[j];
        }
        __syncthreads();
    }

    // Epilogue: out = x + relu(acc + b2)
    float4 b20 = *reinterpret_cast<const float4*>(b2 + tc);
    float4 b21 = *reinterpret_cast<const float4*>(b2 + tc + 4);
#pragma unroll
    for (int i = 0; i < 8; i++) {
        int gr = m0 + tr + i;
        if (gr < NN) {
            const float* xr = X + (size_t)gr * 128 + tc;
            float4 x0 = *reinterpret_cast<const float4*>(xr);
            float4 x1 = *reinterpret_cast<const float4*>(xr + 4);
            float4 o0, o1;
            o0.x = x0.x + fmaxf(acc[i][0] + b20.x, 0.f);
            o0.y = x0.y + fmaxf(acc[i][1] + b20.y, 0.f);
            o0.z = x0.z + fmaxf(acc[i][2] + b20.z, 0.f);
            o0.w = x0.w + fmaxf(acc[i][3] + b20.w, 0.f);
            o1.x = x1.x + fmaxf(acc[i][4] + b21.x, 0.f);
            o1.y = x1.y + fmaxf(acc[i][5] + b21.y, 0.f);
            o1.z = x1.z + fmaxf(acc[i][6] + b21.z, 0.f);
            o1.w = x1.w + fmaxf(acc[i][7] + b21.w, 0.f);
            float* orow = out + (size_t)gr * 128 + tc;
            *reinterpret_cast<float4*>(orow)     = o0;
            *reinterpret_cast<float4*>(orow + 4) = o1;
        }
    }
}

extern "C" void kernel_launch(void* const* d_in, const int* in_sizes, int n_in,
                              void* d_out, int out_size) {
    const float* x    = (const float*)d_in[0];
    const int*   esrc = (const int*)d_in[1];
    const int*   edst = (const int*)d_in[2];
    const float* W1   = (const float*)d_in[3];
    const float* b1   = (const float*)d_in[4];
    const float* W2   = (const float*)d_in[5];
    const float* b2   = (const float*)d_in[6];
    float*       out  = (float*)d_out;

    (void)in_sizes; (void)n_in; (void)out_size;

    // 1. agg = 0
    zero_agg_kernel<<<(NN * DD / 4 + 255) / 256, 256>>>();
    // 2. Y = x @ [W1a | W1b]   (factored edge MLP)
    dim3 gProj((NN + 127) / 128, 2);
    proj_kernel<<<gProj, 256>>>(x, W1);
    // 3. per-edge: agg[dst] += relu(Ya[src] + Yb[dst] + b1)
    edge_kernel<<<(NE + 7) / 8, 256>>>(esrc, edst, b1);
    // 4. out = x + relu([x|agg] @ W2 + b2)
    update_kernel<<<(NN + 127) / 128, 256>>>(x, W2, b2, out);
}

// round 6
// speedup vs baseline: 1.6565x; 1.6565x over previous
#include <cuda_runtime.h>
#include <cstdint>

#define NN 50000
#define NE 600000
#define DD 128

// Scratch (device globals — no allocation in kernel_launch).
static __device__ float g_Y[(size_t)NN * 256];    // [N,256]: 0:128 = x@W1a, 128:256 = x@W1b
static __device__ float g_agg[(size_t)NN * DD];   // segment-summed messages

// ---------------- helpers ----------------
__device__ __forceinline__ uint32_t f2tf32(float f) {
    uint32_t r;
    asm("cvt.rna.tf32.f32 %0, %1;" : "=r"(r) : "f"(f));
    return r;
}

__device__ __forceinline__ void mma_tf32(float* d, const uint32_t* a, const uint32_t* b) {
    asm volatile(
        "mma.sync.aligned.m16n8k8.row.col.f32.tf32.tf32.f32 "
        "{%0,%1,%2,%3}, {%4,%5,%6,%7}, {%8,%9}, {%0,%1,%2,%3};"
        : "+f"(d[0]), "+f"(d[1]), "+f"(d[2]), "+f"(d[3])
        : "r"(a[0]), "r"(a[1]), "r"(a[2]), "r"(a[3]), "r"(b[0]), "r"(b[1]));
}

// SMEM strides (words). A: 16+4 pad -> bank-conflict-free fragment loads.
// B: 128+8 pad -> conflict-free b-frag loads.
#define AS_STRIDE 20
#define BS_STRIDE 136

// ---------------- zero agg ----------------
__global__ void zero_agg_kernel() {
    int i = blockIdx.x * blockDim.x + threadIdx.x;
    if (i < NN * DD / 4)
        reinterpret_cast<float4*>(g_agg)[i] = make_float4(0.f, 0.f, 0.f, 0.f);
}

// =======================================================================
// Shared tf32 GEMM core: C(128x128) = A(128xK) @ B(Kx128)
// 256 threads = 8 warps in 4(m) x 2(n); warp tile 32x64; BK=16.
// A sourced per-kstep via caller-provided pointer logic.
// =======================================================================

struct Frag {
    float acc[2][8][4];
};

__device__ __forceinline__ void gemm_compute_step(const uint32_t* As, const uint32_t* Bs,
                                                  int wm, int wn, int lane, Frag& F) {
    const int g = lane >> 2;
    const int t = lane & 3;
#pragma unroll
    for (int kg = 0; kg < 2; kg++) {
        uint32_t a[2][4];
#pragma unroll
        for (int mt = 0; mt < 2; mt++) {
            int row = wm * 32 + mt * 16 + g;
            int col = kg * 8 + t;
            a[mt][0] = As[row * AS_STRIDE + col];
            a[mt][1] = As[(row + 8) * AS_STRIDE + col];
            a[mt][2] = As[row * AS_STRIDE + col + 4];
            a[mt][3] = As[(row + 8) * AS_STRIDE + col + 4];
        }
#pragma unroll
        for (int nt = 0; nt < 8; nt++) {
            uint32_t b[2];
            int kk = kg * 8 + t;
            int nn = wn * 64 + nt * 8 + g;
            b[0] = Bs[kk * BS_STRIDE + nn];
            b[1] = Bs[(kk + 4) * BS_STRIDE + nn];
            mma_tf32(F.acc[0][nt], a[0], b);
            mma_tf32(F.acc[1][nt], a[1], b);
        }
    }
}

// Load one 128x16 A tile + 16x128 B tile into registers (float4 staging).
__device__ __forceinline__ void gemm_load_regs(const float* __restrict__ Asrc, int m0, int ka,
                                               const float* __restrict__ Bsrc, int kb,
                                               int tid, float4 aR[2], float4 bR[2]) {
#pragma unroll
    for (int p = 0; p < 2; p++) {
        int id = tid + p * 256;
        int r = id >> 2;            // 0..127
        int kc = (id & 3) * 4;      // 0,4,8,12
        int gr = m0 + r;
        aR[p] = make_float4(0.f, 0.f, 0.f, 0.f);
        if (gr < NN)
            aR[p] = *reinterpret_cast<const float4*>(Asrc + (size_t)gr * 128 + ka + kc);
    }
#pragma unroll
    for (int p = 0; p < 2; p++) {
        int id = tid + p * 256;
        int k = id >> 5;            // 0..15
        int nc = (id & 31) * 4;     // 0..124
        bR[p] = *reinterpret_cast<const float4*>(Bsrc + (size_t)(kb + k) * 128 + nc);
    }
}

__device__ __forceinline__ void gemm_store_smem(uint32_t* As, uint32_t* Bs, int tid,
                                                const float4 aR[2], const float4 bR[2]) {
#pragma unroll
    for (int p = 0; p < 2; p++) {
        int id = tid + p * 256;
        int r = id >> 2;
        int kc = (id & 3) * 4;
        uint4 v;
        v.x = f2tf32(aR[p].x); v.y = f2tf32(aR[p].y);
        v.z = f2tf32(aR[p].z); v.w = f2tf32(aR[p].w);
        *reinterpret_cast<uint4*>(&As[r * AS_STRIDE + kc]) = v;
    }
#pragma unroll
    for (int p = 0; p < 2; p++) {
        int id = tid + p * 256;
        int k = id >> 5;
        int nc = (id & 31) * 4;
        uint4 v;
        v.x = f2tf32(bR[p].x); v.y = f2tf32(bR[p].y);
        v.z = f2tf32(bR[p].z); v.w = f2tf32(bR[p].w);
        *reinterpret_cast<uint4*>(&Bs[k * BS_STRIDE + nc]) = v;
    }
}

// ---------------- GEMM 1: Y[:, half*128:+128] = X @ W1[half*128:+128, :] ----------------
__global__ void __launch_bounds__(256) proj_kernel(const float* __restrict__ X,
                                                   const float* __restrict__ W1) {
    __shared__ uint32_t As[128 * AS_STRIDE];
    __shared__ uint32_t Bs[16 * BS_STRIDE];

    const int half = blockIdx.y;
    const float* B = W1 + half * (128 * 128);
    const int m0 = blockIdx.x * 128;

    const int tid  = threadIdx.x;
    const int lane = tid & 31;
    const int wid  = tid >> 5;
    const int wm   = wid & 3;      // 0..3
    const int wn   = wid >> 2;     // 0..1

    Frag F;
#pragma unroll
    for (int mt = 0; mt < 2; mt++)
#pragma unroll
        for (int nt = 0; nt < 8; nt++)
#pragma unroll
            for (int j = 0; j < 4; j++) F.acc[mt][nt][j] = 0.f;

    float4 aR[2], bR[2];
    gemm_load_regs(X, m0, 0, B, 0, tid, aR, bR);

    for (int s = 0; s < 8; s++) {
        __syncthreads();
        gemm_store_smem(As, Bs, tid, aR, bR);
        __syncthreads();
        if (s + 1 < 8)
            gemm_load_regs(X, m0, (s + 1) * 16, B, (s + 1) * 16, tid, aR, bR);
        gemm_compute_step(As, Bs, wm, wn, lane, F);
    }

    // Store Y
    const int g = lane >> 2;
    const int t = lane & 3;
#pragma unroll
    for (int mt = 0; mt < 2; mt++) {
        int row0 = m0 + wm * 32 + mt * 16 + g;
#pragma unroll
        for (int nt = 0; nt < 8; nt++) {
            int col = wn * 64 + nt * 8 + 2 * t;
            if (row0 < NN) {
                float2 v = make_float2(F.acc[mt][nt][0], F.acc[mt][nt][1]);
                *reinterpret_cast<float2*>(g_Y + (size_t)row0 * 256 + half * 128 + col) = v;
            }
            if (row0 + 8 < NN) {
                float2 v = make_float2(F.acc[mt][nt][2], F.acc[mt][nt][3]);
                *reinterpret_cast<float2*>(g_Y + (size_t)(row0 + 8) * 256 + half * 128 + col) = v;
            }
        }
    }
}

// ---------------- Edge pass: agg[dst] += relu(Ya[src] + Yb[dst] + b1) ----------------
__global__ void __launch_bounds__(256) edge_kernel(const int* __restrict__ esrc,
                                                   const int* __restrict__ edst,
                                                   const float* __restrict__ b1) {
    int e = blockIdx.x * 8 + (threadIdx.x >> 5);
    if (e >= NE) return;
    int lane = threadIdx.x & 31;
    int s = __ldg(esrc + e);
    int d = __ldg(edst + e);

    float4 a  = *reinterpret_cast<const float4*>(g_Y + (size_t)s * 256 + lane * 4);
    float4 b  = *reinterpret_cast<const float4*>(g_Y + (size_t)d * 256 + 128 + lane * 4);
    float4 bb = reinterpret_cast<const float4*>(b1)[lane];

    float m0 = fmaxf(a.x + b.x + bb.x, 0.f);
    float m1 = fmaxf(a.y + b.y + bb.y, 0.f);
    float m2 = fmaxf(a.z + b.z + bb.z, 0.f);
    float m3 = fmaxf(a.w + b.w + bb.w, 0.f);

    float* p = g_agg + (size_t)d * DD + lane * 4;
    asm volatile("red.global.add.v4.f32 [%0], {%1, %2, %3, %4};"
                 :: "l"(p), "f"(m0), "f"(m1), "f"(m2), "f"(m3) : "memory");
}

// ---------------- GEMM 2 + epilogue: out = x + relu([x|agg] @ W2 + b2) ----------------
__global__ void __launch_bounds__(256) update_kernel(const float* __restrict__ X,
                                                     const float* __restrict__ W2,
                                                     const float* __restrict__ b2,
                                                     float* __restrict__ out) {
    __shared__ uint32_t As[128 * AS_STRIDE];
    __shared__ uint32_t Bs[16 * BS_STRIDE];

    const int m0 = blockIdx.x * 128;

    const int tid  = threadIdx.x;
    const int lane = tid & 31;
    const int wid  = tid >> 5;
    const int wm   = wid & 3;
    const int wn   = wid >> 2;

    Frag F;
#pragma unroll
    for (int mt = 0; mt < 2; mt++)
#pragma unroll
        for (int nt = 0; nt < 8; nt++)
#pragma unroll
            for (int j = 0; j < 4; j++) F.acc[mt][nt][j] = 0.f;

    float4 aR[2], bR[2];
    gemm_load_regs(X, m0, 0, W2, 0, tid, aR, bR);

    for (int s = 0; s < 16; s++) {
        __syncthreads();
        gemm_store_smem(As, Bs, tid, aR, bR);
        __syncthreads();
        if (s + 1 < 16) {
            int k0 = (s + 1) * 16;
            const float* Asrc = (k0 < 128) ? X : (const float*)g_agg;
            gemm_load_regs(Asrc, m0, k0 & 127, W2, k0, tid, aR, bR);
        }
        gemm_compute_step(As, Bs, wm, wn, lane, F);
    }

    // Epilogue: out = x + relu(acc + b2)
    const int g = lane >> 2;
    const int t = lane & 3;
#pragma unroll
    for (int mt = 0; mt < 2; mt++) {
        int row0 = m0 + wm * 32 + mt * 16 + g;
#pragma unroll
        for (int nt = 0; nt < 8; nt++) {
            int col = wn * 64 + nt * 8 + 2 * t;
            float2 bb = *reinterpret_cast<const float2*>(b2 + col);
            if (row0 < NN) {
                float2 x0 = *reinterpret_cast<const float2*>(X + (size_t)row0 * 128 + col);
                float2 v;
                v.x = x0.x + fmaxf(F.acc[mt][nt][0] + bb.x, 0.f);
                v.y = x0.y + fmaxf(F.acc[mt][nt][1] + bb.y, 0.f);
                *reinterpret_cast<float2*>(out + (size_t)row0 * 128 + col) = v;
            }
            if (row0 + 8 < NN) {
                float2 x1 = *reinterpret_cast<const float2*>(X + (size_t)(row0 + 8) * 128 + col);
                float2 v;
                v.x = x1.x + fmaxf(F.acc[mt][nt][2] + bb.x, 0.f);
                v.y = x1.y + fmaxf(F.acc[mt][nt][3] + bb.y, 0.f);
                *reinterpret_cast<float2*>(out + (size_t)(row0 + 8) * 128 + col) = v;
            }
        }
    }
}

extern "C" void kernel_launch(void* const* d_in, const int* in_sizes, int n_in,
                              void* d_out, int out_size) {
    const float* x    = (const float*)d_in[0];
    const int*   esrc = (const int*)d_in[1];
    const int*   edst = (const int*)d_in[2];
    const float* W1   = (const float*)d_in[3];
    const float* b1   = (const float*)d_in[4];
    const float* W2   = (const float*)d_in[5];
    const float* b2   = (const float*)d_in[6];
    float*       out  = (float*)d_out;

    (void)in_sizes; (void)n_in; (void)out_size;

    // 1. agg = 0
    zero_agg_kernel<<<(NN * DD / 4 + 255) / 256, 256>>>();
    // 2. Y = x @ [W1a | W1b]   (factored edge MLP, tf32 tensor cores)
    dim3 gProj((NN + 127) / 128, 2);
    proj_kernel<<<gProj, 256>>>(x, W1);
    // 3. per-edge: agg[dst] += relu(Ya[src] + Yb[dst] + b1)
    edge_kernel<<<(NE + 7) / 8, 256>>>(esrc, edst, b1);
    // 4. out = x + relu([x|agg] @ W2 + b2)   (tf32 tensor cores)
    update_kernel<<<(NN + 127) / 128, 256>>>(x, W2, b2, out);
}

// round 7
// speedup vs baseline: 1.6979x; 1.0250x over previous
#include <cuda_runtime.h>
#include <cuda_fp16.h>
#include <cstdint>

#define NN 50000
#define NE 600000
#define DD 128

// Scratch (device globals — no allocation in kernel_launch).
static __device__ __half g_Yh[(size_t)NN * 256];  // [N,256] fp16: 0:128 = x@W1a, 128:256 = x@W1b
static __device__ float  g_agg[(size_t)NN * DD];  // segment-summed messages (fp32)

// ---------------- helpers ----------------
__device__ __forceinline__ uint32_t f2tf32(float f) {
    uint32_t r;
    asm("cvt.rna.tf32.f32 %0, %1;" : "=r"(r) : "f"(f));
    return r;
}

__device__ __forceinline__ void mma_tf32(float* d, const uint32_t* a, const uint32_t* b) {
    asm volatile(
        "mma.sync.aligned.m16n8k8.row.col.f32.tf32.tf32.f32 "
        "{%0,%1,%2,%3}, {%4,%5,%6,%7}, {%8,%9}, {%0,%1,%2,%3};"
        : "+f"(d[0]), "+f"(d[1]), "+f"(d[2]), "+f"(d[3])
        : "r"(a[0]), "r"(a[1]), "r"(a[2]), "r"(a[3]), "r"(b[0]), "r"(b[1]));
}

#define AS_STRIDE 20
#define BS_STRIDE 136
#define A_WORDS (128 * AS_STRIDE)
#define B_WORDS (16 * BS_STRIDE)

// ---------------- zero agg ----------------
__global__ void zero_agg_kernel() {
    int i = blockIdx.x * blockDim.x + threadIdx.x;
    if (i < NN * DD / 4)
        reinterpret_cast<float4*>(g_agg)[i] = make_float4(0.f, 0.f, 0.f, 0.f);
}

// =======================================================================
// tf32 GEMM core: C(128x128) = A(128xK) @ B(Kx128), BK=16, double-buffered.
// 256 threads = 8 warps in 4(m) x 2(n); warp tile 32x64.
// =======================================================================

struct Frag {
    float acc[2][8][4];
};

__device__ __forceinline__ void gemm_compute_step(const uint32_t* As, const uint32_t* Bs,
                                                  int wm, int wn, int lane, Frag& F) {
    const int g = lane >> 2;
    const int t = lane & 3;
#pragma unroll
    for (int kg = 0; kg < 2; kg++) {
        uint32_t a[2][4];
#pragma unroll
        for (int mt = 0; mt < 2; mt++) {
            int row = wm * 32 + mt * 16 + g;
            int col = kg * 8 + t;
            a[mt][0] = As[row * AS_STRIDE + col];
            a[mt][1] = As[(row + 8) * AS_STRIDE + col];
            a[mt][2] = As[row * AS_STRIDE + col + 4];
            a[mt][3] = As[(row + 8) * AS_STRIDE + col + 4];
        }
#pragma unroll
        for (int nt = 0; nt < 8; nt++) {
            uint32_t b[2];
            int kk = kg * 8 + t;
            int nn = wn * 64 + nt * 8 + g;
            b[0] = Bs[kk * BS_STRIDE + nn];
            b[1] = Bs[(kk + 4) * BS_STRIDE + nn];
            mma_tf32(F.acc[0][nt], a[0], b);
            mma_tf32(F.acc[1][nt], a[1], b);
        }
    }
}

__device__ __forceinline__ void gemm_load_regs(const float* __restrict__ Asrc, int m0, int ka,
                                               const float* __restrict__ Bsrc, int kb,
                                               int tid, float4 aR[2], float4 bR[2]) {
#pragma unroll
    for (int p = 0; p < 2; p++) {
        int id = tid + p * 256;
        int r = id >> 2;            // 0..127
        int kc = (id & 3) * 4;      // 0,4,8,12
        int gr = m0 + r;
        aR[p] = make_float4(0.f, 0.f, 0.f, 0.f);
        if (gr < NN)
            aR[p] = *reinterpret_cast<const float4*>(Asrc + (size_t)gr * 128 + ka + kc);
    }
#pragma unroll
    for (int p = 0; p < 2; p++) {
        int id = tid + p * 256;
        int k = id >> 5;            // 0..15
        int nc = (id & 31) * 4;     // 0..124
        bR[p] = *reinterpret_cast<const float4*>(Bsrc + (size_t)(kb + k) * 128 + nc);
    }
}

__device__ __forceinline__ void gemm_store_smem(uint32_t* As, uint32_t* Bs, int tid,
                                                const float4 aR[2], const float4 bR[2]) {
#pragma unroll
    for (int p = 0; p < 2; p++) {
        int id = tid + p * 256;
        int r = id >> 2;
        int kc = (id & 3) * 4;
        uint4 v;
        v.x = f2tf32(aR[p].x); v.y = f2tf32(aR[p].y);
        v.z = f2tf32(aR[p].z); v.w = f2tf32(aR[p].w);
        *reinterpret_cast<uint4*>(&As[r * AS_STRIDE + kc]) = v;
    }
#pragma unroll
    for (int p = 0; p < 2; p++) {
        int id = tid + p * 256;
        int k = id >> 5;
        int nc = (id & 31) * 4;
        uint4 v;
        v.x = f2tf32(bR[p].x); v.y = f2tf32(bR[p].y);
        v.z = f2tf32(bR[p].z); v.w = f2tf32(bR[p].w);
        *reinterpret_cast<uint4*>(&Bs[k * BS_STRIDE + nc]) = v;
    }
}

// ---------------- GEMM 1: Yh[:, half*128:+128] = fp16(X @ W1[half*128:+128, :]) ----------------
__global__ void __launch_bounds__(256, 2) proj_kernel(const float* __restrict__ X,
                                                      const float* __restrict__ W1) {
    __shared__ uint32_t As[2][A_WORDS];
    __shared__ uint32_t Bs[2][B_WORDS];

    const int half = blockIdx.y;
    const float* B = W1 + half * (128 * 128);
    const int m0 = blockIdx.x * 128;

    const int tid  = threadIdx.x;
    const int lane = tid & 31;
    const int wid  = tid >> 5;
    const int wm   = wid & 3;
    const int wn   = wid >> 2;

    Frag F;
#pragma unroll
    for (int mt = 0; mt < 2; mt++)
#pragma unroll
        for (int nt = 0; nt < 8; nt++)
#pragma unroll
            for (int j = 0; j < 4; j++) F.acc[mt][nt][j] = 0.f;

    float4 aR[2], bR[2];
    gemm_load_regs(X, m0, 0, B, 0, tid, aR, bR);
    gemm_store_smem(As[0], Bs[0], tid, aR, bR);
    __syncthreads();
    gemm_load_regs(X, m0, 16, B, 16, tid, aR, bR);

#pragma unroll
    for (int s = 0; s < 8; s++) {
        gemm_compute_step(As[s & 1], Bs[s & 1], wm, wn, lane, F);
        if (s + 1 < 8) gemm_store_smem(As[(s + 1) & 1], Bs[(s + 1) & 1], tid, aR, bR);
        __syncthreads();
        if (s + 2 < 8) gemm_load_regs(X, m0, (s + 2) * 16, B, (s + 2) * 16, tid, aR, bR);
    }

    // Epilogue: write fp16 Y
    const int g = lane >> 2;
    const int t = lane & 3;
#pragma unroll
    for (int mt = 0; mt < 2; mt++) {
        int row0 = m0 + wm * 32 + mt * 16 + g;
#pragma unroll
        for (int nt = 0; nt < 8; nt++) {
            int col = wn * 64 + nt * 8 + 2 * t;
            if (row0 < NN) {
                __half2 v = __floats2half2_rn(F.acc[mt][nt][0], F.acc[mt][nt][1]);
                *reinterpret_cast<__half2*>(g_Yh + (size_t)row0 * 256 + half * 128 + col) = v;
            }
            if (row0 + 8 < NN) {
                __half2 v = __floats2half2_rn(F.acc[mt][nt][2], F.acc[mt][nt][3]);
                *reinterpret_cast<__half2*>(g_Yh + (size_t)(row0 + 8) * 256 + half * 128 + col) = v;
            }
        }
    }
}

// ---------------- Edge pass: agg[dst] += relu(Ya[src] + Yb[dst] + b1) ----------------
__global__ void __launch_bounds__(256) edge_kernel(const int* __restrict__ esrc,
                                                   const int* __restrict__ edst,
                                                   const float* __restrict__ b1) {
    int e = blockIdx.x * 8 + (threadIdx.x >> 5);
    if (e >= NE) return;
    int lane = threadIdx.x & 31;
    int s = __ldg(esrc + e);
    int d = __ldg(edst + e);

    uint2 ua = *(reinterpret_cast<const uint2*>(g_Yh + (size_t)s * 256) + lane);
    uint2 ub = *(reinterpret_cast<const uint2*>(g_Yh + (size_t)d * 256 + 128) + lane);
    float4 bb = reinterpret_cast<const float4*>(b1)[lane];

    float2 a01 = __half22float2(*reinterpret_cast<__half2*>(&ua.x));
    float2 a23 = __half22float2(*reinterpret_cast<__half2*>(&ua.y));
    float2 b01 = __half22float2(*reinterpret_cast<__half2*>(&ub.x));
    float2 b23 = __half22float2(*reinterpret_cast<__half2*>(&ub.y));

    float m0 = fmaxf(a01.x + b01.x + bb.x, 0.f);
    float m1 = fmaxf(a01.y + b01.y + bb.y, 0.f);
    float m2 = fmaxf(a23.x + b23.x + bb.z, 0.f);
    float m3 = fmaxf(a23.y + b23.y + bb.w, 0.f);

    float* p = g_agg + (size_t)d * DD + lane * 4;
    asm volatile("red.global.add.v4.f32 [%0], {%1, %2, %3, %4};"
                 :: "l"(p), "f"(m0), "f"(m1), "f"(m2), "f"(m3) : "memory");
}

// ---------------- GEMM 2 + epilogue: out = x + relu([x|agg] @ W2 + b2) ----------------
__global__ void __launch_bounds__(256, 2) update_kernel(const float* __restrict__ X,
                                                        const float* __restrict__ W2,
                                                        const float* __restrict__ b2,
                                                        float* __restrict__ out) {
    __shared__ uint32_t As[2][A_WORDS];
    __shared__ uint32_t Bs[2][B_WORDS];

    const int m0 = blockIdx.x * 128;

    const int tid  = threadIdx.x;
    const int lane = tid & 31;
    const int wid  = tid >> 5;
    const int wm   = wid & 3;
    const int wn   = wid >> 2;

    Frag F;
#pragma unroll
    for (int mt = 0; mt < 2; mt++)
#pragma unroll
        for (int nt = 0; nt < 8; nt++)
#pragma unroll
            for (int j = 0; j < 4; j++) F.acc[mt][nt][j] = 0.f;

    const float* aggp = (const float*)g_agg;

    float4 aR[2], bR[2];
    gemm_load_regs(X, m0, 0, W2, 0, tid, aR, bR);
    gemm_store_smem(As[0], Bs[0], tid, aR, bR);
    __syncthreads();
    gemm_load_regs(X, m0, 16, W2, 16, tid, aR, bR);

#pragma unroll
    for (int s = 0; s < 16; s++) {
        gemm_compute_step(As[s & 1], Bs[s & 1], wm, wn, lane, F);
        if (s + 1 < 16) gemm_store_smem(As[(s + 1) & 1], Bs[(s + 1) & 1], tid, aR, bR);
        __syncthreads();
        if (s + 2 < 16) {
            int step = s + 2;
            const float* Asrc = (step < 8) ? X : aggp;
            gemm_load_regs(Asrc, m0, (step * 16) & 127, W2, step * 16, tid, aR, bR);
        }
    }

    // Epilogue: out = x + relu(acc + b2)
    const int g = lane >> 2;
    const int t = lane & 3;
#pragma unroll
    for (int mt = 0; mt < 2; mt++) {
        int row0 = m0 + wm * 32 + mt * 16 + g;
#pragma unroll
        for (int nt = 0; nt < 8; nt++) {
            int col = wn * 64 + nt * 8 + 2 * t;
            float2 bb = *reinterpret_cast<const float2*>(b2 + col);
            if (row0 < NN) {
                float2 x0 = *reinterpret_cast<const float2*>(X + (size_t)row0 * 128 + col);
                float2 v;
                v.x = x0.x + fmaxf(F.acc[mt][nt][0] + bb.x, 0.f);
                v.y = x0.y + fmaxf(F.acc[mt][nt][1] + bb.y, 0.f);
                *reinterpret_cast<float2*>(out + (size_t)row0 * 128 + col) = v;
            }
            if (row0 + 8 < NN) {
                float2 x1 = *reinterpret_cast<const float2*>(X + (size_t)(row0 + 8) * 128 + col);
                float2 v;
                v.x = x1.x + fmaxf(F.acc[mt][nt][2] + bb.x, 0.f);
                v.y = x1.y + fmaxf(F.acc[mt][nt][3] + bb.y, 0.f);
                *reinterpret_cast<float2*>(out + (size_t)(row0 + 8) * 128 + col) = v;
            }
        }
    }
}

extern "C" void kernel_launch(void* const* d_in, const int* in_sizes, int n_in,
                              void* d_out, int out_size) {
    const float* x    = (const float*)d_in[0];
    const int*   esrc = (const int*)d_in[1];
    const int*   edst = (const int*)d_in[2];
    const float* W1   = (const float*)d_in[3];
    const float* b1   = (const float*)d_in[4];
    const float* W2   = (const float*)d_in[5];
    const float* b2   = (const float*)d_in[6];
    float*       out  = (float*)d_out;

    (void)in_sizes; (void)n_in; (void)out_size;

    // 1. agg = 0
    zero_agg_kernel<<<(NN * DD / 4 + 255) / 256, 256>>>();
    // 2. Yh = fp16(x @ [W1a | W1b])   (factored edge MLP, tf32 tensor cores)
    dim3 gProj((NN + 127) / 128, 2);
    proj_kernel<<<gProj, 256>>>(x, W1);
    // 3. per-edge: agg[dst] += relu(Ya[src] + Yb[dst] + b1)
    edge_kernel<<<(NE + 7) / 8, 256>>>(esrc, edst, b1);
    // 4. out = x + relu([x|agg] @ W2 + b2)   (tf32 tensor cores)
    update_kernel<<<(NN + 127) / 128, 256>>>(x, W2, b2, out);
}

// round 8
// speedup vs baseline: 1.7429x; 1.0265x over previous
#include <cuda_runtime.h>
#include <cuda_fp16.h>
#include <cstdint>

#define NN 50000
#define NE 600000
#define DD 128

// Scratch (device globals — zero-initialized at module load; update_kernel
// re-zeros g_agg after consuming it, so agg==0 at every kernel_launch entry).
static __device__ __half g_Yh[(size_t)NN * 256];  // [N,256] fp16: 0:128 = x@W1a, 128:256 = x@W1b
static __device__ float  g_agg[(size_t)NN * DD];  // segment-summed messages (fp32)

// ---------------- helpers ----------------
__device__ __forceinline__ uint32_t f2tf32(float f) {
    uint32_t r;
    asm("cvt.rna.tf32.f32 %0, %1;" : "=r"(r) : "f"(f));
    return r;
}

__device__ __forceinline__ void mma_tf32(float* d, const uint32_t* a, const uint32_t* b) {
    asm volatile(
        "mma.sync.aligned.m16n8k8.row.col.f32.tf32.tf32.f32 "
        "{%0,%1,%2,%3}, {%4,%5,%6,%7}, {%8,%9}, {%0,%1,%2,%3};"
        : "+f"(d[0]), "+f"(d[1]), "+f"(d[2]), "+f"(d[3])
        : "r"(a[0]), "r"(a[1]), "r"(a[2]), "r"(a[3]), "r"(b[0]), "r"(b[1]));
}

__device__ __forceinline__ void cp16(uint32_t dst_smem, const void* src, int src_bytes) {
    asm volatile("cp.async.cg.shared.global [%0], [%1], 16, %2;"
                 :: "r"(dst_smem), "l"(src), "r"(src_bytes));
}
__device__ __forceinline__ void cp_commit() { asm volatile("cp.async.commit_group;"); }
template <int N>
__device__ __forceinline__ void cp_wait() { asm volatile("cp.async.wait_group %0;" :: "n"(N)); }

// SMEM strides (words). A: 16+4 pad, B: 128+8 pad -> conflict-free frag loads.
#define AS_STRIDE 20
#define BS_STRIDE 136
#define A_STAGE_WORDS (128 * AS_STRIDE)          // 2560
#define B_STAGE_WORDS (16 * BS_STRIDE)           // 2176
#define STAGE_WORDS (A_STAGE_WORDS + B_STAGE_WORDS)  // 4736
#define NSTAGE 3
#define SMEM_BYTES (NSTAGE * STAGE_WORDS * 4)    // 56832

// =======================================================================
// tf32 GEMM core: C(128x128) = A(128xK) @ B(Kx128), BK=16, cp.async 3-stage.
// 256 threads = 8 warps in 4(m) x 2(n); warp tile 32x64.
// =======================================================================

struct Frag { float acc[2][8][4]; };

__device__ __forceinline__ void gemm_compute_step(const float* As, const float* Bs,
                                                  int wm, int wn, int lane, Frag& F) {
    const int g = lane >> 2;
    const int t = lane & 3;
#pragma unroll
    for (int kg = 0; kg < 2; kg++) {
        uint32_t a[2][4];
#pragma unroll
        for (int mt = 0; mt < 2; mt++) {
            int row = wm * 32 + mt * 16 + g;
            int col = kg * 8 + t;
            a[mt][0] = f2tf32(As[row * AS_STRIDE + col]);
            a[mt][1] = f2tf32(As[(row + 8) * AS_STRIDE + col]);
            a[mt][2] = f2tf32(As[row * AS_STRIDE + col + 4]);
            a[mt][3] = f2tf32(As[(row + 8) * AS_STRIDE + col + 4]);
        }
#pragma unroll
        for (int nt = 0; nt < 8; nt++) {
            int kk = kg * 8 + t;
            int nn = wn * 64 + nt * 8 + g;
            uint32_t b[2];
            b[0] = f2tf32(Bs[kk * BS_STRIDE + nn]);
            b[1] = f2tf32(Bs[(kk + 4) * BS_STRIDE + nn]);
            mma_tf32(F.acc[0][nt], a[0], b);
            mma_tf32(F.acc[1][nt], a[1], b);
        }
    }
}

// Issue cp.async for one BK=16 tile: A rows m0..m0+127 cols ka..ka+15 from Asrc,
// B rows kb..kb+15 from Bsrc (128 cols).
__device__ __forceinline__ void gemm_issue_stage(uint32_t smem_stage,
                                                 const float* __restrict__ Asrc, int m0, int ka,
                                                 const float* __restrict__ Bsrc, int kb,
                                                 int tid) {
#pragma unroll
    for (int p = 0; p < 2; p++) {
        int id = tid + p * 256;
        int r  = id >> 2;           // 0..127
        int kc = (id & 3) * 4;      // 0,4,8,12
        int gr = m0 + r;
        int ok = (gr < NN) ? 16 : 0;
        int grc = (gr < NN) ? gr : (NN - 1);
        cp16(smem_stage + (r * AS_STRIDE + kc) * 4,
             Asrc + (size_t)grc * 128 + ka + kc, ok);
    }
#pragma unroll
    for (int p = 0; p < 2; p++) {
        int id = tid + p * 256;
        int k  = id >> 5;           // 0..15
        int nc = (id & 31) * 4;     // 0..124
        cp16(smem_stage + (A_STAGE_WORDS + k * BS_STRIDE + nc) * 4,
             Bsrc + (size_t)(kb + k) * 128 + nc, 16);
    }
    cp_commit();
}

// ---------------- GEMM 1: Yh[:, half*128:+128] = fp16(X @ W1[half*128:+128, :]) ----------------
__global__ void __launch_bounds__(256, 2) proj_kernel(const float* __restrict__ X,
                                                      const float* __restrict__ W1) {
    extern __shared__ float sm[];
    const uint32_t smem_base = (uint32_t)__cvta_generic_to_shared(sm);

    const int half = blockIdx.y;
    const float* B = W1 + half * (128 * 128);
    const int m0 = blockIdx.x * 128;

    const int tid  = threadIdx.x;
    const int lane = tid & 31;
    const int wid  = tid >> 5;
    const int wm   = wid & 3;
    const int wn   = wid >> 2;

    Frag F;
#pragma unroll
    for (int mt = 0; mt < 2; mt++)
#pragma unroll
        for (int nt = 0; nt < 8; nt++)
#pragma unroll
            for (int j = 0; j < 4; j++) F.acc[mt][nt][j] = 0.f;

    const int NS = 8;  // K=128 / 16
    gemm_issue_stage(smem_base + 0 * STAGE_WORDS * 4, X, m0, 0,  B, 0,  tid);
    gemm_issue_stage(smem_base + 1 * STAGE_WORDS * 4, X, m0, 16, B, 16, tid);

#pragma unroll 1
    for (int s = 0; s < NS; s++) {
        cp_wait<1>();
        __syncthreads();
        int nxt = s + 2;
        if (nxt < NS)
            gemm_issue_stage(smem_base + (nxt % NSTAGE) * STAGE_WORDS * 4,
                             X, m0, nxt * 16, B, nxt * 16, tid);
        const float* stage = sm + (s % NSTAGE) * STAGE_WORDS;
        gemm_compute_step(stage, stage + A_STAGE_WORDS, wm, wn, lane, F);
    }

    // Epilogue: write fp16 Y
    const int g = lane >> 2;
    const int t = lane & 3;
#pragma unroll
    for (int mt = 0; mt < 2; mt++) {
        int row0 = m0 + wm * 32 + mt * 16 + g;
#pragma unroll
        for (int nt = 0; nt < 8; nt++) {
            int col = wn * 64 + nt * 8 + 2 * t;
            if (row0 < NN) {
                __half2 v = __floats2half2_rn(F.acc[mt][nt][0], F.acc[mt][nt][1]);
                *reinterpret_cast<__half2*>(g_Yh + (size_t)row0 * 256 + half * 128 + col) = v;
            }
            if (row0 + 8 < NN) {
                __half2 v = __floats2half2_rn(F.acc[mt][nt][2], F.acc[mt][nt][3]);
                *reinterpret_cast<__half2*>(g_Yh + (size_t)(row0 + 8) * 256 + half * 128 + col) = v;
            }
        }
    }
}

// ---------------- Edge pass: agg[dst] += relu(Ya[src] + Yb[dst] + b1) ----------------
__global__ void __launch_bounds__(256) edge_kernel(const int* __restrict__ esrc,
                                                   const int* __restrict__ edst,
                                                   const float* __restrict__ b1) {
    int e = blockIdx.x * 8 + (threadIdx.x >> 5);
    if (e >= NE) return;
    int lane = threadIdx.x & 31;
    int s = __ldg(esrc + e);
    int d = __ldg(edst + e);

    uint2 ua = *(reinterpret_cast<const uint2*>(g_Yh + (size_t)s * 256) + lane);
    uint2 ub = *(reinterpret_cast<const uint2*>(g_Yh + (size_t)d * 256 + 128) + lane);
    float4 bb = reinterpret_cast<const float4*>(b1)[lane];

    float2 a01 = __half22float2(*reinterpret_cast<__half2*>(&ua.x));
    float2 a23 = __half22float2(*reinterpret_cast<__half2*>(&ua.y));
    float2 b01 = __half22float2(*reinterpret_cast<__half2*>(&ub.x));
    float2 b23 = __half22float2(*reinterpret_cast<__half2*>(&ub.y));

    float m0 = fmaxf(a01.x + b01.x + bb.x, 0.f);
    float m1 = fmaxf(a01.y + b01.y + bb.y, 0.f);
    float m2 = fmaxf(a23.x + b23.x + bb.z, 0.f);
    float m3 = fmaxf(a23.y + b23.y + bb.w, 0.f);

    float* p = g_agg + (size_t)d * DD + lane * 4;
    asm volatile("red.global.add.v4.f32 [%0], {%1, %2, %3, %4};"
                 :: "l"(p), "f"(m0), "f"(m1), "f"(m2), "f"(m3) : "memory");
}

// ---------------- GEMM 2 + epilogue: out = x + relu([x|agg] @ W2 + b2); re-zero agg ----------------
__global__ void __launch_bounds__(256, 2) update_kernel(const float* __restrict__ X,
                                                        const float* __restrict__ W2,
                                                        const float* __restrict__ b2,
                                                        float* __restrict__ out) {
    extern __shared__ float sm[];
    const uint32_t smem_base = (uint32_t)__cvta_generic_to_shared(sm);

    const int m0 = blockIdx.x * 128;

    const int tid  = threadIdx.x;
    const int lane = tid & 31;
    const int wid  = tid >> 5;
    const int wm   = wid & 3;
    const int wn   = wid >> 2;

    Frag F;
#pragma unroll
    for (int mt = 0; mt < 2; mt++)
#pragma unroll
        for (int nt = 0; nt < 8; nt++)
#pragma unroll
            for (int j = 0; j < 4; j++) F.acc[mt][nt][j] = 0.f;

    const float* aggp = (const float*)g_agg;
    const int NS = 16;  // K=256 / 16

    gemm_issue_stage(smem_base + 0 * STAGE_WORDS * 4, X, m0, 0,  W2, 0,  tid);
    gemm_issue_stage(smem_base + 1 * STAGE_WORDS * 4, X, m0, 16, W2, 16, tid);

#pragma unroll 1
    for (int s = 0; s < NS; s++) {
        cp_wait<1>();
        __syncthreads();
        int nxt = s + 2;
        if (nxt < NS) {
            const float* Asrc = (nxt < 8) ? X : aggp;
            gemm_issue_stage(smem_base + (nxt % NSTAGE) * STAGE_WORDS * 4,
                             Asrc, m0, (nxt * 16) & 127, W2, nxt * 16, tid);
        }
        const float* stage = sm + (s % NSTAGE) * STAGE_WORDS;
        gemm_compute_step(stage, stage + A_STAGE_WORDS, wm, wn, lane, F);
    }

    // Epilogue: out = x + relu(acc + b2)
    const int g = lane >> 2;
    const int t = lane & 3;
#pragma unroll
    for (int mt = 0; mt < 2; mt++) {
        int row0 = m0 + wm * 32 + mt * 16 + g;
#pragma unroll
        for (int nt = 0; nt < 8; nt++) {
            int col = wn * 64 + nt * 8 + 2 * t;
            float2 bb = *reinterpret_cast<const float2*>(b2 + col);
            if (row0 < NN) {
                float2 x0 = *reinterpret_cast<const float2*>(X + (size_t)row0 * 128 + col);
                float2 v;
                v.x = x0.x + fmaxf(F.acc[mt][nt][0] + bb.x, 0.f);
                v.y = x0.y + fmaxf(F.acc[mt][nt][1] + bb.y, 0.f);
                *reinterpret_cast<float2*>(out + (size_t)row0 * 128 + col) = v;
            }
            if (row0 + 8 < NN) {
                float2 x1 = *reinterpret_cast<const float2*>(X + (size_t)(row0 + 8) * 128 + col);
                float2 v;
                v.x = x1.x + fmaxf(F.acc[mt][nt][2] + bb.x, 0.f);
                v.y = x1.y + fmaxf(F.acc[mt][nt][3] + bb.y, 0.f);
                *reinterpret_cast<float2*>(out + (size_t)(row0 + 8) * 128 + col) = v;
            }
        }
    }

    // Re-zero this CTA's agg rows (only this CTA ever read them) so agg==0
    // at the next kernel_launch entry.
    float* aggw = g_agg;
#pragma unroll
    for (int i = tid; i < 128 * 32; i += 256) {
        int r = i >> 5;
        int c = (i & 31) * 4;
        int gr = m0 + r;
        if (gr < NN)
            *reinterpret_cast<float4*>(aggw + (size_t)gr * 128 + c) =
                make_float4(0.f, 0.f, 0.f, 0.f);
    }
}

extern "C" void kernel_launch(void* const* d_in, const int* in_sizes, int n_in,
                              void* d_out, int out_size) {
    const float* x    = (const float*)d_in[0];
    const int*   esrc = (const int*)d_in[1];
    const int*   edst = (const int*)d_in[2];
    const float* W1   = (const float*)d_in[3];
    const float* b1   = (const float*)d_in[4];
    const float* W2   = (const float*)d_in[5];
    const float* b2   = (const float*)d_in[6];
    float*       out  = (float*)d_out;

    (void)in_sizes; (void)n_in; (void)out_size;

    cudaFuncSetAttribute(proj_kernel,   cudaFuncAttributeMaxDynamicSharedMemorySize, SMEM_BYTES);
    cudaFuncSetAttribute(update_kernel, cudaFuncAttributeMaxDynamicSharedMemorySize, SMEM_BYTES);

    // 1. Yh = fp16(x @ [W1a | W1b])   (factored edge MLP, tf32 + cp.async pipeline)
    dim3 gProj((NN + 127) / 128, 2);
    proj_kernel<<<gProj, 256, SMEM_BYTES>>>(x, W1);
    // 2. per-edge: agg[dst] += relu(Ya[src] + Yb[dst] + b1)   (agg==0 on entry)
    edge_kernel<<<(NE + 7) / 8, 256>>>(esrc, edst, b1);
    // 3. out = x + relu([x|agg] @ W2 + b2); epilogue re-zeros agg
    update_kernel<<<(NN + 127) / 128, 256, SMEM_BYTES>>>(x, W2, b2, out);
}